// round 9
// baseline (speedup 1.0000x reference)
#include <cuda_runtime.h>
#include <cuda_bf16.h>
#include <math.h>
#include <stdint.h>

#define SUB_KEYS   512
#define KEY_DIM    256
#define VALUE_DIM  512
#define TOPK       32
#define D_MODEL    1024
#define LN_EPS     1e-5f
#define MAX_TOKENS 8192

typedef unsigned long long u64;
typedef unsigned int u32;

// ---------------- scratch (device globals) ------------------------------------
__device__ __nv_bfloat16 g_xh  [MAX_TOKENS * D_MODEL];
__device__ __nv_bfloat16 g_wqT [2 * KEY_DIM * D_MODEL];   // [512,1024]
__device__ __nv_bfloat16 g_cah [SUB_KEYS * KEY_DIM];
__device__ __nv_bfloat16 g_cbh [SUB_KEYS * KEY_DIM];
__device__ __nv_bfloat16 g_woT [D_MODEL * VALUE_DIM];     // [1024,512]
__device__ __nv_bfloat16 g_qh  [MAX_TOKENS * 2 * KEY_DIM];
__device__ __nv_bfloat16 g_outh[MAX_TOKENS * VALUE_DIM];
__device__ float g_sa[MAX_TOKENS * SUB_KEYS];
__device__ float g_sb[MAX_TOKENS * SUB_KEYS];
__device__ float g_y [MAX_TOKENS * D_MODEL];

__device__ __forceinline__ u32 smem_u32(const void* p) {
    return (u32)__cvta_generic_to_shared(p);
}

// ---------------- portable tensor-core GEMM (mma.sync bf16) -------------------
// C[M,N] = A[M,K](row bf16) @ B[N,K](row bf16)^T (+bias +resid)
// Block 128x128, BK=64, 256 threads (8 warps 4x2), cp.async double-buffer.
#define BM 128
#define BN 128
#define BKK 64
#define LDS_P 72                 // row pitch in elems (144B: conflict-free LDSM)
#define TILE_E (BM * LDS_P)      // elems per buffer
#define GEMM_SMEM (2 * 2 * TILE_E * 2)   // 73728 bytes

__device__ __forceinline__ void cp16(u32 saddr, const void* g) {
    asm volatile("cp.async.cg.shared.global [%0], [%1], 16;" :: "r"(saddr), "l"(g));
}
__device__ __forceinline__ void cp_commit() { asm volatile("cp.async.commit_group;"); }
template <int N> __device__ __forceinline__ void cp_wait() {
    asm volatile("cp.async.wait_group %0;" :: "n"(N));
}
__device__ __forceinline__ void ldsm4(u32& r0, u32& r1, u32& r2, u32& r3, u32 a) {
    asm volatile("ldmatrix.sync.aligned.m8n8.x4.shared.b16 {%0,%1,%2,%3}, [%4];"
                 : "=r"(r0), "=r"(r1), "=r"(r2), "=r"(r3) : "r"(a));
}
__device__ __forceinline__ void mma16816(float* d, const u32* a, u32 b0, u32 b1) {
    asm volatile(
        "mma.sync.aligned.m16n8k16.row.col.f32.bf16.bf16.f32 "
        "{%0,%1,%2,%3}, {%4,%5,%6,%7}, {%8,%9}, {%0,%1,%2,%3};"
        : "+f"(d[0]), "+f"(d[1]), "+f"(d[2]), "+f"(d[3])
        : "r"(a[0]), "r"(a[1]), "r"(a[2]), "r"(a[3]), "r"(b0), "r"(b1));
}

template <bool OB, bool HB, bool HR>
__device__ __forceinline__ void gemm_mma_body(
    const __nv_bfloat16* __restrict__ A, int lda,
    const __nv_bfloat16* __restrict__ B, int ldb,
    void* __restrict__ Cv, int ldc, int K,
    const float* __restrict__ bias, const float* __restrict__ resid)
{
    extern __shared__ __nv_bfloat16 sm[];
    __nv_bfloat16* sA = sm;                 // [2][128][LDS_P]
    __nv_bfloat16* sB = sm + 2 * TILE_E;    // [2][128][LDS_P]

    const int t = threadIdx.x;
    const int wid = t >> 5, lane = t & 31;
    const int wm = wid >> 1, wn = wid & 1;
    const int m0 = blockIdx.y * BM, n0 = blockIdx.x * BN;

    // loader mapping: thread t -> row t>>1 (0..127), col half (t&1)*32,
    // 4 x 16B chunks per tile per thread => full 128x64 coverage.
    const int rw  = t >> 1;
    const int ch  = (t & 1) * 32;
    const int nct = K / BKK;

    // preload stage 0
#pragma unroll
    for (int p = 0; p < 4; p++) {
        cp16(smem_u32(sA + (size_t)rw * LDS_P + ch + p * 8),
             A + (size_t)(m0 + rw) * lda + ch + p * 8);
        cp16(smem_u32(sB + (size_t)rw * LDS_P + ch + p * 8),
             B + (size_t)(n0 + rw) * ldb + ch + p * 8);
    }
    cp_commit();

    float acc[2][8][4];
#pragma unroll
    for (int i = 0; i < 2; i++)
#pragma unroll
        for (int j = 0; j < 8; j++)
#pragma unroll
            for (int q = 0; q < 4; q++) acc[i][j][q] = 0.f;

    const int a_row = (lane & 15);
    const int a_col = (lane >> 4) << 3;
    const int b_row = ((lane >> 4) << 3) + (lane & 7);
    const int b_col = (lane & 8) ? 8 : 0;

    for (int c = 0; c < nct; c++) {
        const int buf = c & 1;
        if (c + 1 < nct) {
            const int nb = buf ^ 1;
            const int kb = (c + 1) * BKK + ch;
#pragma unroll
            for (int p = 0; p < 4; p++) {
                cp16(smem_u32(sA + (size_t)nb * TILE_E + (size_t)rw * LDS_P + ch + p * 8),
                     A + (size_t)(m0 + rw) * lda + kb + p * 8);
                cp16(smem_u32(sB + (size_t)nb * TILE_E + (size_t)rw * LDS_P + ch + p * 8),
                     B + (size_t)(n0 + rw) * ldb + kb + p * 8);
            }
            cp_commit();
            cp_wait<1>();
        } else {
            cp_wait<0>();
        }
        __syncthreads();

        const __nv_bfloat16* bA = sA + (size_t)buf * TILE_E;
        const __nv_bfloat16* bB = sB + (size_t)buf * TILE_E;
#pragma unroll
        for (int ks = 0; ks < 4; ks++) {
            u32 afr[2][4];
#pragma unroll
            for (int mt = 0; mt < 2; mt++)
                ldsm4(afr[mt][0], afr[mt][1], afr[mt][2], afr[mt][3],
                      smem_u32(bA + (size_t)(wm * 32 + mt * 16 + a_row) * LDS_P + ks * 16 + a_col));
            u32 bfr[4][4];
#pragma unroll
            for (int p = 0; p < 4; p++)
                ldsm4(bfr[p][0], bfr[p][1], bfr[p][2], bfr[p][3],
                      smem_u32(bB + (size_t)(wn * 64 + p * 16 + b_row) * LDS_P + ks * 16 + b_col));
#pragma unroll
            for (int mt = 0; mt < 2; mt++)
#pragma unroll
                for (int p = 0; p < 4; p++) {
                    mma16816(acc[mt][p * 2 + 0], afr[mt], bfr[p][0], bfr[p][1]);
                    mma16816(acc[mt][p * 2 + 1], afr[mt], bfr[p][2], bfr[p][3]);
                }
        }
        __syncthreads();
    }

    // ---- epilogue ----
    const int gp = lane >> 2, tg = lane & 3;
#pragma unroll
    for (int mt = 0; mt < 2; mt++) {
#pragma unroll
        for (int half = 0; half < 2; half++) {
            const int m = m0 + wm * 32 + mt * 16 + gp + half * 8;
#pragma unroll
            for (int nt = 0; nt < 8; nt++) {
                const int n = n0 + wn * 64 + nt * 8 + tg * 2;
                float v0 = acc[mt][nt][half * 2 + 0];
                float v1 = acc[mt][nt][half * 2 + 1];
                if (HB) { v0 += bias[n]; v1 += bias[n + 1]; }
                if (HR) {
                    const float2 r = *(const float2*)(resid + (size_t)m * ldc + n);
                    v0 += r.x; v1 += r.y;
                }
                if (OB) {
                    *(__nv_bfloat162*)((__nv_bfloat16*)Cv + (size_t)m * ldc + n) =
                        __floats2bfloat162_rn(v0, v1);
                } else {
                    *(float2*)((float*)Cv + (size_t)m * ldc + n) = make_float2(v0, v1);
                }
            }
        }
    }
}

__global__ __launch_bounds__(256, 2) void k_gemm_q(const float* __restrict__ bq) {
    gemm_mma_body<true, true, false>(g_xh, D_MODEL, g_wqT, D_MODEL, g_qh,
                                     2 * KEY_DIM, D_MODEL, bq, nullptr);
}
__global__ __launch_bounds__(256, 2) void k_gemm_s() {
    if (blockIdx.z == 0)
        gemm_mma_body<false, false, false>(g_qh, 2 * KEY_DIM, g_cah, KEY_DIM, g_sa,
                                           SUB_KEYS, KEY_DIM, nullptr, nullptr);
    else
        gemm_mma_body<false, false, false>(g_qh + KEY_DIM, 2 * KEY_DIM, g_cbh, KEY_DIM, g_sb,
                                           SUB_KEYS, KEY_DIM, nullptr, nullptr);
}
__global__ __launch_bounds__(256, 2) void k_gemm_y(const float* __restrict__ bo,
                                                   const float* __restrict__ x) {
    gemm_mma_body<false, true, true>(g_outh, VALUE_DIM, g_woT, VALUE_DIM, g_y,
                                     D_MODEL, VALUE_DIM, bo, x);
}

// ---------------- fused prep: cvt x/ca/cb + transpose Wq/Wo -------------------
__global__ __launch_bounds__(256) void k_prep(
    const float* __restrict__ x, const float* __restrict__ ca,
    const float* __restrict__ cb, const float* __restrict__ Wq,
    const float* __restrict__ Wo, int nx)
{
    __shared__ float tile[32][33];
    const int b = blockIdx.x, t = threadIdx.x;

    const float* s = nullptr;
    __nv_bfloat16* d = nullptr;
    int bb = 0;

    if (b < nx + 128) {
        if (b < nx)            { s = x;  d = g_xh;  bb = b; }
        else if (b < nx + 64)  { s = ca; d = g_cah; bb = b - nx; }
        else                   { s = cb; d = g_cbh; bb = b - nx - 64; }
        const int i = bb * 2048 + t * 8;
        float4 a = *(const float4*)(s + i), c = *(const float4*)(s + i + 4);
        __nv_bfloat162 h[4];
        h[0] = __float22bfloat162_rn(make_float2(a.x, a.y));
        h[1] = __float22bfloat162_rn(make_float2(a.z, a.w));
        h[2] = __float22bfloat162_rn(make_float2(c.x, c.y));
        h[3] = __float22bfloat162_rn(make_float2(c.z, c.w));
        *(uint4*)(d + i) = *(uint4*)h;
        return;
    }
    int R, C, bx, by;
    if (b < nx + 128 + 512) {
        bb = b - nx - 128;  s = Wq; d = g_wqT; R = D_MODEL; C = 2 * KEY_DIM;
        bx = (bb & 15) * 32; by = (bb >> 4) * 32;
    } else {
        bb = b - nx - 128 - 512; s = Wo; d = g_woT; R = VALUE_DIM; C = D_MODEL;
        bx = (bb & 31) * 32; by = (bb >> 5) * 32;
    }
    const int tx = t & 31, ty = t >> 5;
#pragma unroll
    for (int j = 0; j < 32; j += 8)
        tile[ty + j][tx] = s[(size_t)(by + ty + j) * C + bx + tx];
    __syncthreads();
#pragma unroll
    for (int j = 0; j < 32; j += 8)
        d[(size_t)(bx + ty + j) * R + by + tx] = __float2bfloat16(tile[tx][ty + j]);
}

// ---------------- top-k + softmax + gather ------------------------------------
__constant__ unsigned char c_ci[128] = {
    0,0,0,0,0,0,0,0,0,0,0,0,0,0,0,0,0,0,0,0,0,0,0,0,0,0,0,0,0,0,0,0,
    1,1,1,1,1,1,1,1,1,1,1,1,1,1,1,1,
    2,2,2,2,2,2,2,2,2,2, 3,3,3,3,3,3,3,3, 4,4,4,4,4,4, 5,5,5,5,5,
    6,6,6,6, 7,7,7,7, 8,8,8, 9,9,9, 10,10, 11,11, 12,12, 13,13, 14,14, 15,15,
    16,17,18,19,20,21,22,23,24,25,26,27,28,29,30,31, 0,0,0,0,0,0,0,0,0};
__constant__ unsigned char c_cj[128] = {
    0,1,2,3,4,5,6,7,8,9,10,11,12,13,14,15,16,17,18,19,20,21,22,23,24,25,26,27,28,29,30,31,
    0,1,2,3,4,5,6,7,8,9,10,11,12,13,14,15,
    0,1,2,3,4,5,6,7,8,9, 0,1,2,3,4,5,6,7, 0,1,2,3,4,5, 0,1,2,3,4,
    0,1,2,3, 0,1,2,3, 0,1,2, 0,1,2, 0,1, 0,1, 0,1, 0,1, 0,1, 0,1,
    0,0,0,0,0,0,0,0,0,0,0,0,0,0,0,0, 0,0,0,0,0,0,0,0,0};

__device__ __forceinline__ u32 fsort(float f) {
    u32 b = __float_as_uint(f);
    return b ^ ((b & 0x80000000u) ? 0xFFFFFFFFu : 0x80000000u);
}
__device__ __forceinline__ float funsort(u32 u) {
    return __uint_as_float((u & 0x80000000u) ? (u ^ 0x80000000u) : ~u);
}

__global__ __launch_bounds__(256) void topk_gather_kernel(
    const float* __restrict__ values, int NT)
{
    const int w = threadIdx.x >> 5, lane = threadIdx.x & 31;
    const int token = blockIdx.x * 8 + w;
    if (token >= NT) return;

    __shared__ u64   s_keys[8][16][32];
    __shared__ float s_av[8][32], s_bv[8][32], s_fs[8][32], s_w[8][32];
    __shared__ int   s_ai[8][32], s_bi[8][32], s_fi[8][32];

    // ---- stage 1: exact top-32 per side ----
#pragma unroll 1
    for (int side = 0; side < 2; side++) {
        const float* sc = (side == 0 ? g_sa : g_sb) + (size_t)token * SUB_KEYS;
        u64 key[16];
#pragma unroll
        for (int v = 0; v < 4; v++) {
            float4 f = *(const float4*)(sc + lane * 16 + v * 4);
            int b = lane * 16 + v * 4;
            key[v*4+0] = ((u64)fsort(f.x) << 16) | (u32)(0xFFFF - (b+0));
            key[v*4+1] = ((u64)fsort(f.y) << 16) | (u32)(0xFFFF - (b+1));
            key[v*4+2] = ((u64)fsort(f.z) << 16) | (u32)(0xFFFF - (b+2));
            key[v*4+3] = ((u64)fsort(f.w) << 16) | (u32)(0xFFFF - (b+3));
        }
#pragma unroll
        for (int size = 2; size <= 16; size <<= 1)
#pragma unroll
            for (int stride = size >> 1; stride > 0; stride >>= 1)
#pragma unroll
                for (int i = 0; i < 16; i++) {
                    int j = i ^ stride;
                    if (j > i) {
                        bool dir = ((i & size) == 0);
                        u64 a = key[i], b = key[j];
                        bool sw = dir ? (a < b) : (a > b);
                        key[i] = sw ? b : a;
                        key[j] = sw ? a : b;
                    }
                }
#pragma unroll
        for (int i = 0; i < 16; i++) s_keys[w][i][lane] = key[i];
        __syncwarp();

        int cnt = 0;
        for (int it = 0; it < TOPK; it++) {
            int cc = cnt < 15 ? cnt : 15;
            u64 head = s_keys[w][cc][lane];
            if (cnt > 15) head = 0;
            u32 hi = (u32)(head >> 16);
            u32 lo = (u32)(head & 0xFFFFu);
            u32 mhi = __reduce_max_sync(0xffffffffu, hi);
            u32 mlo = __reduce_max_sync(0xffffffffu, (hi == mhi) ? lo : 0u);
            if (hi == mhi && lo == mlo) cnt++;
            if (lane == it) {
                int idx = 0xFFFF - (int)mlo;
                float fv = funsort(mhi);
                if (side == 0) { s_av[w][it] = fv; s_ai[w][it] = idx; }
                else           { s_bv[w][it] = fv; s_bi[w][it] = idx; }
            }
        }
        __syncwarp();
    }

    // ---- stage 2: dominance-pruned cartesian top-32 (119 cands) ----
    u64 ck[4];
#pragma unroll
    for (int s = 0; s < 4; s++) {
        int c = lane * 4 + s;
        int i = c_ci[c], j = c_cj[c];
        float sum = s_av[w][i] + s_bv[w][j];
        ck[s] = (c < 119) ? (((u64)fsort(sum) << 16) | (u32)(0xFFFF - (i * 32 + j))) : 0ull;
    }
    for (int it = 0; it < TOPK; it++) {
        u64 m = ck[0];
#pragma unroll
        for (int s = 1; s < 4; s++) if (ck[s] > m) m = ck[s];
        u32 hi = (u32)(m >> 16);
        u32 lo = (u32)(m & 0xFFFFu);
        u32 mhi = __reduce_max_sync(0xffffffffu, hi);
        u32 mlo = __reduce_max_sync(0xffffffffu, (hi == mhi) ? lo : 0u);
        u64 wk = ((u64)mhi << 16) | mlo;
#pragma unroll
        for (int s = 0; s < 4; s++) if (ck[s] == wk) ck[s] = 0;
        if (lane == it) {
            int pp = 0xFFFF - (int)mlo;
            s_fs[w][it] = funsort(mhi);
            s_fi[w][it] = s_ai[w][pp >> 5] * SUB_KEYS + s_bi[w][pp & 31];
        }
    }
    __syncwarp();

    // ---- softmax ----
    float f = s_fs[w][lane];
    float mx = f;
#pragma unroll
    for (int off = 16; off > 0; off >>= 1)
        mx = fmaxf(mx, __shfl_xor_sync(0xffffffffu, mx, off));
    float e = expf(f - mx);
    float sum = e;
#pragma unroll
    for (int off = 16; off > 0; off >>= 1)
        sum += __shfl_xor_sync(0xffffffffu, sum, off);
    s_w[w][lane] = e / sum;
    __syncwarp();

    // ---- weighted gather ----
    float4 a0 = {0,0,0,0}, a1 = {0,0,0,0}, a2 = {0,0,0,0}, a3 = {0,0,0,0};
#pragma unroll 4
    for (int r = 0; r < TOPK; r++) {
        const float wt = s_w[w][r];
        const float4* vr = (const float4*)(values + (size_t)s_fi[w][r] * VALUE_DIM) + lane * 4;
        float4 v0 = vr[0], v1 = vr[1], v2 = vr[2], v3 = vr[3];
        a0.x = fmaf(wt, v0.x, a0.x); a0.y = fmaf(wt, v0.y, a0.y);
        a0.z = fmaf(wt, v0.z, a0.z); a0.w = fmaf(wt, v0.w, a0.w);
        a1.x = fmaf(wt, v1.x, a1.x); a1.y = fmaf(wt, v1.y, a1.y);
        a1.z = fmaf(wt, v1.z, a1.z); a1.w = fmaf(wt, v1.w, a1.w);
        a2.x = fmaf(wt, v2.x, a2.x); a2.y = fmaf(wt, v2.y, a2.y);
        a2.z = fmaf(wt, v2.z, a2.z); a2.w = fmaf(wt, v2.w, a2.w);
        a3.x = fmaf(wt, v3.x, a3.x); a3.y = fmaf(wt, v3.y, a3.y);
        a3.z = fmaf(wt, v3.z, a3.z); a3.w = fmaf(wt, v3.w, a3.w);
    }
    __nv_bfloat162 h[8];
    h[0] = __float22bfloat162_rn(make_float2(a0.x, a0.y));
    h[1] = __float22bfloat162_rn(make_float2(a0.z, a0.w));
    h[2] = __float22bfloat162_rn(make_float2(a1.x, a1.y));
    h[3] = __float22bfloat162_rn(make_float2(a1.z, a1.w));
    h[4] = __float22bfloat162_rn(make_float2(a2.x, a2.y));
    h[5] = __float22bfloat162_rn(make_float2(a2.z, a2.w));
    h[6] = __float22bfloat162_rn(make_float2(a3.x, a3.y));
    h[7] = __float22bfloat162_rn(make_float2(a3.z, a3.w));
    __nv_bfloat16* o = g_outh + (size_t)token * VALUE_DIM + lane * 16;
    *(uint4*)o       = *(uint4*)(h);
    *(uint4*)(o + 8) = *(uint4*)(h + 4);
}

// ---------------- LayerNorm ---------------------------------------------------
__global__ __launch_bounds__(256) void ln_kernel(
    const float* __restrict__ gamma, const float* __restrict__ beta,
    float* __restrict__ out)
{
    const int row = blockIdx.x;
    const int tid = threadIdx.x;
    const float* yr = g_y + (size_t)row * D_MODEL;

    float v[4];
    float s = 0.f, ss = 0.f;
#pragma unroll
    for (int j = 0; j < 4; j++) {
        v[j] = yr[tid + 256 * j];
        s += v[j]; ss += v[j] * v[j];
    }
#pragma unroll
    for (int off = 16; off > 0; off >>= 1) {
        s  += __shfl_xor_sync(0xffffffffu, s, off);
        ss += __shfl_xor_sync(0xffffffffu, ss, off);
    }
    __shared__ float red_s[8], red_ss[8], s_mu, s_rstd;
    const int wid = tid >> 5, lane = tid & 31;
    if (lane == 0) { red_s[wid] = s; red_ss[wid] = ss; }
    __syncthreads();
    if (tid == 0) {
        float S = 0.f, SS = 0.f;
#pragma unroll
        for (int i = 0; i < 8; i++) { S += red_s[i]; SS += red_ss[i]; }
        float mu = S * (1.f / D_MODEL);
        s_mu = mu;
        s_rstd = rsqrtf(SS * (1.f / D_MODEL) - mu * mu + LN_EPS);
    }
    __syncthreads();
    const float mu = s_mu, rstd = s_rstd;
    float* orow = out + (size_t)row * D_MODEL;
#pragma unroll
    for (int j = 0; j < 4; j++) {
        int c = tid + 256 * j;
        orow[c] = (v[j] - mu) * rstd * gamma[c] + beta[c];
    }
}

// ---------------- launch ------------------------------------------------------
extern "C" void kernel_launch(void* const* d_in, const int* in_sizes, int n_in,
                              void* d_out, int out_size)
{
    const float* x      = (const float*)d_in[0];
    const float* Wq     = (const float*)d_in[1];
    const float* bq     = (const float*)d_in[2];
    const float* ca     = (const float*)d_in[3];
    const float* cb     = (const float*)d_in[4];
    const float* values = (const float*)d_in[5];
    const float* Wo     = (const float*)d_in[6];
    const float* bo     = (const float*)d_in[7];
    const float* gamma  = (const float*)d_in[8];
    const float* beta   = (const float*)d_in[9];
    float* out = (float*)d_out;

    const int NT = in_sizes[0] / D_MODEL;   // 8192

    cudaFuncSetAttribute(k_gemm_q, cudaFuncAttributeMaxDynamicSharedMemorySize, GEMM_SMEM);
    cudaFuncSetAttribute(k_gemm_s, cudaFuncAttributeMaxDynamicSharedMemorySize, GEMM_SMEM);
    cudaFuncSetAttribute(k_gemm_y, cudaFuncAttributeMaxDynamicSharedMemorySize, GEMM_SMEM);

    const int nx = (NT * D_MODEL) / 2048;

    k_prep<<<dim3(nx + 128 + 1024), 256>>>(x, ca, cb, Wq, Wo, nx);
    k_gemm_q<<<dim3(2 * KEY_DIM / BN, NT / BM), 256, GEMM_SMEM>>>(bq);
    k_gemm_s<<<dim3(SUB_KEYS / BN, NT / BM, 2), 256, GEMM_SMEM>>>();
    topk_gather_kernel<<<dim3((NT + 7) / 8), 256>>>(values, NT);
    k_gemm_y<<<dim3(D_MODEL / BN, NT / BM), 256, GEMM_SMEM>>>(bo, x);
    ln_kernel<<<dim3(NT), 256>>>(gamma, beta, out);
}